// round 7
// baseline (speedup 1.0000x reference)
#include <cuda_runtime.h>

// SO3 sparse CG tensor product, LMAX=2 (S=9), N_FEAT=128.
//   out[a, io, f] = sum_p cg[p] * x1[a, i1[p], f] * x2[a, i2[p], f]
//
// SINGLE fused kernel. Hardcoded 83-triple support (compile-time -> register-
// resident unrolled f32x2 FMA chain). Each block matches the runtime cg_sparse
// structure against the hardcoded support inline, hidden under the input LDG
// latency (loads issued first). Structure mismatch -> generic fallback branch.
// Block = 128 threads = 4 atoms x 32 float4-lanes (this shape measured fastest;
// larger blocks regress via cross-CTA L1tex-queue contention).

// X(slot, i1, i2, io) — 83 triples, grouped by io.
#define PATHS(X) \
  X(0,0,0,0) X(1,1,1,0) X(2,2,2,0) X(3,3,3,0) X(4,4,4,0) X(5,5,5,0) X(6,6,6,0) X(7,7,7,0) X(8,8,8,0) \
  X(9,0,1,1) X(10,1,0,1) X(11,1,6,1) X(12,1,8,1) X(13,3,4,1) X(14,2,5,1) X(15,6,1,1) X(16,8,1,1) X(17,4,3,1) X(18,5,2,1) \
  X(19,0,2,2) X(20,2,0,2) X(21,1,5,2) X(22,2,6,2) X(23,3,7,2) X(24,5,1,2) X(25,6,2,2) X(26,7,3,2) \
  X(27,0,3,3) X(28,3,0,3) X(29,1,4,3) X(30,2,7,3) X(31,3,6,3) X(32,3,8,3) X(33,4,1,3) X(34,7,2,3) X(35,6,3,3) X(36,8,3,3) \
  X(37,0,4,4) X(38,4,0,4) X(39,1,3,4) X(40,3,1,4) X(41,4,6,4) X(42,5,7,4) X(43,6,4,4) X(44,7,5,4) \
  X(45,0,5,5) X(46,5,0,5) X(47,1,2,5) X(48,2,1,5) X(49,4,7,5) X(50,5,6,5) X(51,5,8,5) X(52,6,5,5) X(53,7,4,5) X(54,8,5,5) \
  X(55,0,6,6) X(56,6,0,6) X(57,1,1,6) X(58,2,2,6) X(59,3,3,6) X(60,4,4,6) X(61,5,5,6) X(62,6,6,6) X(63,7,7,6) X(64,8,8,6) \
  X(65,0,7,7) X(66,7,0,7) X(67,2,3,7) X(68,3,2,7) X(69,4,5,7) X(70,5,4,7) X(71,6,7,7) X(72,7,6,7) X(73,7,8,7) X(74,8,7,7) \
  X(75,0,8,8) X(76,8,0,8) X(77,1,1,8) X(78,3,3,8) X(79,5,5,8) X(80,6,8,8) X(81,7,7,8) X(82,8,6,8)

#define NSLOT 83
#define MAXP  768

#define X(s, a, b, c) (((a) << 8) | ((b) << 4) | (c)),
__constant__ int c_trip[NSLOT] = { PATHS(X) };
#undef X

#define NTHREADS 128
#define ATOMS_PER_BLOCK 4   // one warp per atom, 32 float4-threads per row

__global__ __launch_bounds__(NTHREADS)
void so3_tp_kernel(const float* __restrict__ x1,
                   const float* __restrict__ x2,
                   float* __restrict__ out,
                   int natoms,
                   const float* __restrict__ cg,
                   const int* __restrict__ i1,
                   const int* __restrict__ i2,
                   const int* __restrict__ io,
                   int P) {
    __shared__ int   s_code[MAXP];
    __shared__ float s_val[MAXP];
    __shared__ unsigned long long s_cg[NSLOT];

    const int tid  = threadIdx.x;
    const int a_in = tid >> 5;          // atom within block
    const int lane = tid & 31;          // float4 index within 128-feature row
    const long long atom = (long long)blockIdx.x * ATOMS_PER_BLOCK + a_in;
    const int active = atom < natoms;

    const long long base = atom * 1152 + (long long)lane * 4;  // floats

    // ---- Phase A: issue the 18 streaming LDG.128s first (latency hiding) ----
    ulonglong2 x1r[9], x2r[9];
    if (active) {
#pragma unroll
        for (int s = 0; s < 9; ++s) {
            x1r[s] = __ldg(reinterpret_cast<const ulonglong2*>(x1 + base + s * 128));
            x2r[s] = __ldg(reinterpret_cast<const ulonglong2*>(x2 + base + s * 128));
        }
    }

    // ---- Phase B: inline CG structure matching (hidden under Phase A) ----
    int ok = (P <= MAXP) ? 1 : 0;
    const int Pc = (P <= MAXP) ? P : MAXP;

    for (int p = tid; p < Pc; p += NTHREADS) {
        const int a = __ldg(i1 + p), b = __ldg(i2 + p), c = __ldg(io + p);
        int code = -1;
        if (a >= 0 && a <= 8 && b >= 0 && b <= 8 && c >= 0 && c <= 8)
            code = (a << 8) | (b << 4) | c;
        else
            ok = 0;
        s_code[p] = code;
        s_val[p]  = __ldg(cg + p);
    }
    __syncthreads();

    if (tid < NSLOT) {
        const int code = c_trip[tid];
        float v = 0.0f;
        for (int p = 0; p < Pc; ++p)
            if (s_code[p] == code) v += s_val[p];
        const unsigned int u = __float_as_uint(v);
        s_cg[tid] = ((unsigned long long)u << 32) | (unsigned long long)u;
    }

    for (int p = tid; p < Pc; p += NTHREADS) {
        const int code = s_code[p];
        int found = 0;
#pragma unroll 1
        for (int t = 0; t < NSLOT; ++t)
            if (c_trip[t] == code) { found = 1; break; }
        if (!found) ok = 0;
    }

    // Barrier (publishes s_cg) + block-wide AND of structure validity.
    const int ok_all = __syncthreads_and(ok);

    if (!active) return;

    if (ok_all) {
        // ---- fast path: register-resident, packed f32x2 ----
        ulonglong2 acc[9];
#pragma unroll
        for (int s = 0; s < 9; ++s) { acc[s].x = 0ull; acc[s].y = 0ull; }
        unsigned long long t0, t1;
#define X(s, a, b, c)                                                       \
        {                                                                   \
            const unsigned long long cg2 = s_cg[s];                         \
            asm("mul.rn.f32x2 %0, %1, %2;"                                  \
                : "=l"(t0) : "l"(x1r[a].x), "l"(x2r[b].x));                 \
            asm("mul.rn.f32x2 %0, %1, %2;"                                  \
                : "=l"(t1) : "l"(x1r[a].y), "l"(x2r[b].y));                 \
            asm("fma.rn.f32x2 %0, %1, %2, %3;"                              \
                : "=l"(acc[c].x) : "l"(t0), "l"(cg2), "l"(acc[c].x));       \
            asm("fma.rn.f32x2 %0, %1, %2, %3;"                              \
                : "=l"(acc[c].y) : "l"(t1), "l"(cg2), "l"(acc[c].y));       \
        }
        PATHS(X)
#undef X
#pragma unroll
        for (int s = 0; s < 9; ++s) {
            *reinterpret_cast<ulonglong2*>(out + base + s * 128) = acc[s];
        }
    } else {
        // ---- generic fallback: always correct for any sparse structure ----
        float4 acc[9];
#pragma unroll
        for (int s = 0; s < 9; ++s) acc[s] = make_float4(0.f, 0.f, 0.f, 0.f);
#pragma unroll 1
        for (int p = 0; p < P; ++p) {
            const int a = i1[p], b = i2[p], c = io[p];
            if (a < 0 || a > 8 || b < 0 || b > 8 || c < 0 || c > 8) continue;
            const float v = cg[p];
            const float4 u = *reinterpret_cast<const float4*>(x1 + base + a * 128);
            const float4 w = *reinterpret_cast<const float4*>(x2 + base + b * 128);
            acc[c].x += v * u.x * w.x;
            acc[c].y += v * u.y * w.y;
            acc[c].z += v * u.z * w.z;
            acc[c].w += v * u.w * w.w;
        }
#pragma unroll
        for (int s = 0; s < 9; ++s)
            *reinterpret_cast<float4*>(out + base + s * 128) = acc[s];
    }
}

extern "C" void kernel_launch(void* const* d_in, const int* in_sizes, int n_in,
                              void* d_out, int out_size) {
    const float* x1 = (const float*)d_in[0];
    const float* x2 = (const float*)d_in[1];
    const float* cg = (const float*)d_in[2];
    const int*   i1 = (const int*)d_in[3];
    const int*   i2 = (const int*)d_in[4];
    const int*   io = (const int*)d_in[5];
    float* out = (float*)d_out;

    const int P      = in_sizes[2];
    const int natoms = in_sizes[0] / (9 * 128);

    const int nblocks = (natoms + ATOMS_PER_BLOCK - 1) / ATOMS_PER_BLOCK;
    so3_tp_kernel<<<nblocks, NTHREADS>>>(x1, x2, out, natoms, cg, i1, i2, io, P);
}

// round 8
// speedup vs baseline: 1.4423x; 1.4423x over previous
#include <cuda_runtime.h>

// SO3 sparse CG tensor product, LMAX=2 (S=9), N_FEAT=128.
//   out[a, io, f] = sum_p cg[p] * x1[a, i1[p], f] * x2[a, i2[p], f]
//
// SINGLE fused kernel. Hardcoded 83-triple support (compile-time -> register-
// resident unrolled f32x2 FMA chain). Per-block runtime-structure matching via
// a compile-time perfect-hash table (code -> slot), O(P) per block, hidden
// under the 18 streaming LDG.128s. Mismatch -> generic fallback (always
// correct). Block = 128 threads = 4 atoms x 32 float4-lanes (measured-best
// shape; larger blocks regress via cross-CTA L1tex-queue contention).

// X(slot, i1, i2, io) — 83 triples, grouped by io.
#define PATHS(X) \
  X(0,0,0,0) X(1,1,1,0) X(2,2,2,0) X(3,3,3,0) X(4,4,4,0) X(5,5,5,0) X(6,6,6,0) X(7,7,7,0) X(8,8,8,0) \
  X(9,0,1,1) X(10,1,0,1) X(11,1,6,1) X(12,1,8,1) X(13,3,4,1) X(14,2,5,1) X(15,6,1,1) X(16,8,1,1) X(17,4,3,1) X(18,5,2,1) \
  X(19,0,2,2) X(20,2,0,2) X(21,1,5,2) X(22,2,6,2) X(23,3,7,2) X(24,5,1,2) X(25,6,2,2) X(26,7,3,2) \
  X(27,0,3,3) X(28,3,0,3) X(29,1,4,3) X(30,2,7,3) X(31,3,6,3) X(32,3,8,3) X(33,4,1,3) X(34,7,2,3) X(35,6,3,3) X(36,8,3,3) \
  X(37,0,4,4) X(38,4,0,4) X(39,1,3,4) X(40,3,1,4) X(41,4,6,4) X(42,5,7,4) X(43,6,4,4) X(44,7,5,4) \
  X(45,0,5,5) X(46,5,0,5) X(47,1,2,5) X(48,2,1,5) X(49,4,7,5) X(50,5,6,5) X(51,5,8,5) X(52,6,5,5) X(53,7,4,5) X(54,8,5,5) \
  X(55,0,6,6) X(56,6,0,6) X(57,1,1,6) X(58,2,2,6) X(59,3,3,6) X(60,4,4,6) X(61,5,5,6) X(62,6,6,6) X(63,7,7,6) X(64,8,8,6) \
  X(65,0,7,7) X(66,7,0,7) X(67,2,3,7) X(68,3,2,7) X(69,4,5,7) X(70,5,4,7) X(71,6,7,7) X(72,7,6,7) X(73,7,8,7) X(74,8,7,7) \
  X(75,0,8,8) X(76,8,0,8) X(77,1,1,8) X(78,3,3,8) X(79,5,5,8) X(80,6,8,8) X(81,7,7,8) X(82,8,6,8)

#define NSLOT 83

// Compile-time perfect-hash table: (a*81 + b*9 + c) -> slot, 0xFF = absent.
struct SlotTbl { unsigned char m[729]; };
static constexpr SlotTbl make_slot_tbl() {
    SlotTbl t{};
    for (int i = 0; i < 729; ++i) t.m[i] = 0xFF;
#define X(s, a, b, c) t.m[(a) * 81 + (b) * 9 + (c)] = (unsigned char)(s);
    PATHS(X)
#undef X
    return t;
}
__constant__ SlotTbl c_slot = make_slot_tbl();

#define NTHREADS 128
#define ATOMS_PER_BLOCK 4   // one warp per atom, 32 float4-threads per row

__global__ __launch_bounds__(NTHREADS)
void so3_tp_kernel(const float* __restrict__ x1,
                   const float* __restrict__ x2,
                   float* __restrict__ out,
                   int natoms,
                   const float* __restrict__ cg,
                   const int* __restrict__ i1,
                   const int* __restrict__ i2,
                   const int* __restrict__ io,
                   int P) {
    __shared__ float              s_cgf[NSLOT];
    __shared__ unsigned long long s_cg[NSLOT];

    const int tid  = threadIdx.x;
    const int a_in = tid >> 5;          // atom within block
    const int lane = tid & 31;          // float4 index within 128-feature row
    const long long atom = (long long)blockIdx.x * ATOMS_PER_BLOCK + a_in;
    const int active = atom < natoms;

    const long long base = atom * 1152 + (long long)lane * 4;  // floats

    // ---- Phase A: issue the 18 streaming LDG.128s first (latency hiding) ----
    ulonglong2 x1r[9], x2r[9];
    if (active) {
#pragma unroll
        for (int s = 0; s < 9; ++s) {
            x1r[s] = __ldg(reinterpret_cast<const ulonglong2*>(x1 + base + s * 128));
            x2r[s] = __ldg(reinterpret_cast<const ulonglong2*>(x2 + base + s * 128));
        }
    }

    // ---- Phase B: O(P) perfect-hash structure matching (hidden) ----
    if (tid < NSLOT) s_cgf[tid] = 0.0f;
    __syncthreads();

    int ok = 1;
    for (int p = tid; p < P; p += NTHREADS) {
        const int a = __ldg(i1 + p), b = __ldg(i2 + p), c = __ldg(io + p);
        const float v = __ldg(cg + p);
        if (a >= 0 && a <= 8 && b >= 0 && b <= 8 && c >= 0 && c <= 8) {
            const unsigned char slot = c_slot.m[a * 81 + b * 9 + c];
            if (slot != 0xFF)
                atomicAdd(&s_cgf[slot], v);
            else
                ok = 0;
        } else {
            ok = 0;
        }
    }
    const int ok_all = __syncthreads_and(ok);

    // Pack (cg, cg) pairs for f32x2 operands.
    if (tid < NSLOT) {
        const unsigned int u = __float_as_uint(s_cgf[tid]);
        s_cg[tid] = ((unsigned long long)u << 32) | (unsigned long long)u;
    }
    __syncthreads();

    if (!active) return;

    if (ok_all) {
        // ---- fast path: register-resident, packed f32x2 ----
        ulonglong2 acc[9];
#pragma unroll
        for (int s = 0; s < 9; ++s) { acc[s].x = 0ull; acc[s].y = 0ull; }
        unsigned long long t0, t1;
#define X(s, a, b, c)                                                       \
        {                                                                   \
            const unsigned long long cg2 = s_cg[s];                         \
            asm("mul.rn.f32x2 %0, %1, %2;"                                  \
                : "=l"(t0) : "l"(x1r[a].x), "l"(x2r[b].x));                 \
            asm("mul.rn.f32x2 %0, %1, %2;"                                  \
                : "=l"(t1) : "l"(x1r[a].y), "l"(x2r[b].y));                 \
            asm("fma.rn.f32x2 %0, %1, %2, %3;"                              \
                : "=l"(acc[c].x) : "l"(t0), "l"(cg2), "l"(acc[c].x));       \
            asm("fma.rn.f32x2 %0, %1, %2, %3;"                              \
                : "=l"(acc[c].y) : "l"(t1), "l"(cg2), "l"(acc[c].y));       \
        }
        PATHS(X)
#undef X
#pragma unroll
        for (int s = 0; s < 9; ++s) {
            *reinterpret_cast<ulonglong2*>(out + base + s * 128) = acc[s];
        }
    } else {
        // ---- generic fallback: always correct for any sparse structure ----
        float4 acc[9];
#pragma unroll
        for (int s = 0; s < 9; ++s) acc[s] = make_float4(0.f, 0.f, 0.f, 0.f);
#pragma unroll 1
        for (int p = 0; p < P; ++p) {
            const int a = i1[p], b = i2[p], c = io[p];
            if (a < 0 || a > 8 || b < 0 || b > 8 || c < 0 || c > 8) continue;
            const float v = cg[p];
            const float4 u = *reinterpret_cast<const float4*>(x1 + base + a * 128);
            const float4 w = *reinterpret_cast<const float4*>(x2 + base + b * 128);
            acc[c].x += v * u.x * w.x;
            acc[c].y += v * u.y * w.y;
            acc[c].z += v * u.z * w.z;
            acc[c].w += v * u.w * w.w;
        }
#pragma unroll
        for (int s = 0; s < 9; ++s)
            *reinterpret_cast<float4*>(out + base + s * 128) = acc[s];
    }
}

extern "C" void kernel_launch(void* const* d_in, const int* in_sizes, int n_in,
                              void* d_out, int out_size) {
    const float* x1 = (const float*)d_in[0];
    const float* x2 = (const float*)d_in[1];
    const float* cg = (const float*)d_in[2];
    const int*   i1 = (const int*)d_in[3];
    const int*   i2 = (const int*)d_in[4];
    const int*   io = (const int*)d_in[5];
    float* out = (float*)d_out;

    const int P      = in_sizes[2];
    const int natoms = in_sizes[0] / (9 * 128);

    const int nblocks = (natoms + ATOMS_PER_BLOCK - 1) / ATOMS_PER_BLOCK;
    so3_tp_kernel<<<nblocks, NTHREADS>>>(x1, x2, out, natoms, cg, i1, i2, io, P);
}

// round 9
// speedup vs baseline: 1.4634x; 1.0146x over previous
#include <cuda_runtime.h>

// SO3 sparse CG tensor product, LMAX=2 (S=9), N_FEAT=128.
//   out[a, io, f] = sum_p cg[p] * x1[a, i1[p], f] * x2[a, i2[p], f]
//
// SINGLE fused kernel. Hardcoded 83-triple support (compile-time -> register-
// resident unrolled f32x2 FMA chain). Per-block runtime-structure matching via
// a compile-time perfect-hash table (code -> slot), O(P) per block, hidden
// under the 18 streaming LDG.128s. Only TWO block barriers on the critical
// path: consumers read the f32 cg directly from shared and pack their own
// (cg,cg) f32x2 operand with mov.b64. Mismatch -> generic fallback (always
// correct). Block = 128 threads = 4 atoms x 32 float4-lanes (measured-best
// shape; larger blocks regress via cross-CTA L1tex-queue contention).

// X(slot, i1, i2, io) — 83 triples, grouped by io.
#define PATHS(X) \
  X(0,0,0,0) X(1,1,1,0) X(2,2,2,0) X(3,3,3,0) X(4,4,4,0) X(5,5,5,0) X(6,6,6,0) X(7,7,7,0) X(8,8,8,0) \
  X(9,0,1,1) X(10,1,0,1) X(11,1,6,1) X(12,1,8,1) X(13,3,4,1) X(14,2,5,1) X(15,6,1,1) X(16,8,1,1) X(17,4,3,1) X(18,5,2,1) \
  X(19,0,2,2) X(20,2,0,2) X(21,1,5,2) X(22,2,6,2) X(23,3,7,2) X(24,5,1,2) X(25,6,2,2) X(26,7,3,2) \
  X(27,0,3,3) X(28,3,0,3) X(29,1,4,3) X(30,2,7,3) X(31,3,6,3) X(32,3,8,3) X(33,4,1,3) X(34,7,2,3) X(35,6,3,3) X(36,8,3,3) \
  X(37,0,4,4) X(38,4,0,4) X(39,1,3,4) X(40,3,1,4) X(41,4,6,4) X(42,5,7,4) X(43,6,4,4) X(44,7,5,4) \
  X(45,0,5,5) X(46,5,0,5) X(47,1,2,5) X(48,2,1,5) X(49,4,7,5) X(50,5,6,5) X(51,5,8,5) X(52,6,5,5) X(53,7,4,5) X(54,8,5,5) \
  X(55,0,6,6) X(56,6,0,6) X(57,1,1,6) X(58,2,2,6) X(59,3,3,6) X(60,4,4,6) X(61,5,5,6) X(62,6,6,6) X(63,7,7,6) X(64,8,8,6) \
  X(65,0,7,7) X(66,7,0,7) X(67,2,3,7) X(68,3,2,7) X(69,4,5,7) X(70,5,4,7) X(71,6,7,7) X(72,7,6,7) X(73,7,8,7) X(74,8,7,7) \
  X(75,0,8,8) X(76,8,0,8) X(77,1,1,8) X(78,3,3,8) X(79,5,5,8) X(80,6,8,8) X(81,7,7,8) X(82,8,6,8)

#define NSLOT 83

// Compile-time perfect-hash table: (a*81 + b*9 + c) -> slot, 0xFF = absent.
struct SlotTbl { unsigned char m[729]; };
static constexpr SlotTbl make_slot_tbl() {
    SlotTbl t{};
    for (int i = 0; i < 729; ++i) t.m[i] = 0xFF;
#define X(s, a, b, c) t.m[(a) * 81 + (b) * 9 + (c)] = (unsigned char)(s);
    PATHS(X)
#undef X
    return t;
}
__constant__ SlotTbl c_slot = make_slot_tbl();

#define NTHREADS 128
#define ATOMS_PER_BLOCK 4   // one warp per atom, 32 float4-threads per row

__global__ __launch_bounds__(NTHREADS)
void so3_tp_kernel(const float* __restrict__ x1,
                   const float* __restrict__ x2,
                   float* __restrict__ out,
                   int natoms,
                   const float* __restrict__ cg,
                   const int* __restrict__ i1,
                   const int* __restrict__ i2,
                   const int* __restrict__ io,
                   int P) {
    __shared__ float s_cgf[NSLOT];

    const int tid  = threadIdx.x;
    const int a_in = tid >> 5;          // atom within block
    const int lane = tid & 31;          // float4 index within 128-feature row
    const long long atom = (long long)blockIdx.x * ATOMS_PER_BLOCK + a_in;
    const int active = atom < natoms;

    const long long base = atom * 1152 + (long long)lane * 4;  // floats

    // ---- Phase A: issue the 18 streaming LDG.128s first (latency hiding) ----
    ulonglong2 x1r[9], x2r[9];
    if (active) {
#pragma unroll
        for (int s = 0; s < 9; ++s) {
            x1r[s] = __ldg(reinterpret_cast<const ulonglong2*>(x1 + base + s * 128));
            x2r[s] = __ldg(reinterpret_cast<const ulonglong2*>(x2 + base + s * 128));
        }
    }

    // ---- Phase B: O(P) perfect-hash structure matching (hidden) ----
    if (tid < NSLOT) s_cgf[tid] = 0.0f;
    __syncthreads();

    int ok = 1;
    for (int p = tid; p < P; p += NTHREADS) {
        const int a = __ldg(i1 + p), b = __ldg(i2 + p), c = __ldg(io + p);
        const float v = __ldg(cg + p);
        if (a >= 0 && a <= 8 && b >= 0 && b <= 8 && c >= 0 && c <= 8) {
            const unsigned char slot = c_slot.m[a * 81 + b * 9 + c];
            if (slot != 0xFF)
                atomicAdd(&s_cgf[slot], v);
            else
                ok = 0;
        } else {
            ok = 0;
        }
    }
    // Single barrier: publishes s_cgf AND reduces structure validity.
    const int ok_all = __syncthreads_and(ok);

    if (!active) return;

    if (ok_all) {
        // ---- fast path: register-resident, packed f32x2 ----
        ulonglong2 acc[9];
#pragma unroll
        for (int s = 0; s < 9; ++s) { acc[s].x = 0ull; acc[s].y = 0ull; }
        unsigned long long t0, t1;
#define X(s, a, b, c)                                                       \
        {                                                                   \
            const float cgf = s_cgf[s];                                     \
            unsigned long long cg2;                                         \
            asm("mov.b64 %0, {%1, %1};" : "=l"(cg2) : "f"(cgf));            \
            asm("mul.rn.f32x2 %0, %1, %2;"                                  \
                : "=l"(t0) : "l"(x1r[a].x), "l"(x2r[b].x));                 \
            asm("mul.rn.f32x2 %0, %1, %2;"                                  \
                : "=l"(t1) : "l"(x1r[a].y), "l"(x2r[b].y));                 \
            asm("fma.rn.f32x2 %0, %1, %2, %3;"                              \
                : "=l"(acc[c].x) : "l"(t0), "l"(cg2), "l"(acc[c].x));       \
            asm("fma.rn.f32x2 %0, %1, %2, %3;"                              \
                : "=l"(acc[c].y) : "l"(t1), "l"(cg2), "l"(acc[c].y));       \
        }
        PATHS(X)
#undef X
#pragma unroll
        for (int s = 0; s < 9; ++s) {
            *reinterpret_cast<ulonglong2*>(out + base + s * 128) = acc[s];
        }
    } else {
        // ---- generic fallback: always correct for any sparse structure ----
        float4 acc[9];
#pragma unroll
        for (int s = 0; s < 9; ++s) acc[s] = make_float4(0.f, 0.f, 0.f, 0.f);
#pragma unroll 1
        for (int p = 0; p < P; ++p) {
            const int a = i1[p], b = i2[p], c = io[p];
            if (a < 0 || a > 8 || b < 0 || b > 8 || c < 0 || c > 8) continue;
            const float v = cg[p];
            const float4 u = *reinterpret_cast<const float4*>(x1 + base + a * 128);
            const float4 w = *reinterpret_cast<const float4*>(x2 + base + b * 128);
            acc[c].x += v * u.x * w.x;
            acc[c].y += v * u.y * w.y;
            acc[c].z += v * u.z * w.z;
            acc[c].w += v * u.w * w.w;
        }
#pragma unroll
        for (int s = 0; s < 9; ++s)
            *reinterpret_cast<float4*>(out + base + s * 128) = acc[s];
    }
}

extern "C" void kernel_launch(void* const* d_in, const int* in_sizes, int n_in,
                              void* d_out, int out_size) {
    const float* x1 = (const float*)d_in[0];
    const float* x2 = (const float*)d_in[1];
    const float* cg = (const float*)d_in[2];
    const int*   i1 = (const int*)d_in[3];
    const int*   i2 = (const int*)d_in[4];
    const int*   io = (const int*)d_in[5];
    float* out = (float*)d_out;

    const int P      = in_sizes[2];
    const int natoms = in_sizes[0] / (9 * 128);

    const int nblocks = (natoms + ATOMS_PER_BLOCK - 1) / ATOMS_PER_BLOCK;
    so3_tp_kernel<<<nblocks, NTHREADS>>>(x1, x2, out, natoms, cg, i1, i2, io, P);
}

// round 12
// speedup vs baseline: 1.5008x; 1.0255x over previous
#include <cuda_runtime.h>

// SO3 sparse CG tensor product, LMAX=2 (S=9), N_FEAT=128.
//   out[a, io, f] = sum_p cg[p] * x1[a, i1[p], f] * x2[a, i2[p], f]
//
// SINGLE fused kernel. Hardcoded 83-triple support (compile-time -> register-
// resident unrolled f32x2 FMA chain), per-block O(P) perfect-hash matching of
// the runtime cg_sparse structure hidden under the streaming loads; mismatch
// -> generic fallback. This revision: (a) evict-first (.cs) loads AND stores —
// data is touched exactly once, keep it out of L2; (b) per-io-group compute +
// immediate store: only one 16B accumulator live at a time (regs ~100, 5
// CTAs/SM) and stores interleave with FMA work. Block = 128 threads = 4 atoms
// x 32 float4-lanes (measured-best; larger blocks regress via cross-CTA
// L1tex-queue contention).

// Per-output-group path lists: XG(slot, i1, i2). Union = the 83-triple support.
#define PATHS_IO0(X) X(0,0,0) X(1,1,1) X(2,2,2) X(3,3,3) X(4,4,4) X(5,5,5) X(6,6,6) X(7,7,7) X(8,8,8)
#define PATHS_IO1(X) X(9,0,1) X(10,1,0) X(11,1,6) X(12,1,8) X(13,3,4) X(14,2,5) X(15,6,1) X(16,8,1) X(17,4,3) X(18,5,2)
#define PATHS_IO2(X) X(19,0,2) X(20,2,0) X(21,1,5) X(22,2,6) X(23,3,7) X(24,5,1) X(25,6,2) X(26,7,3)
#define PATHS_IO3(X) X(27,0,3) X(28,3,0) X(29,1,4) X(30,2,7) X(31,3,6) X(32,3,8) X(33,4,1) X(34,7,2) X(35,6,3) X(36,8,3)
#define PATHS_IO4(X) X(37,0,4) X(38,4,0) X(39,1,3) X(40,3,1) X(41,4,6) X(42,5,7) X(43,6,4) X(44,7,5)
#define PATHS_IO5(X) X(45,0,5) X(46,5,0) X(47,1,2) X(48,2,1) X(49,4,7) X(50,5,6) X(51,5,8) X(52,6,5) X(53,7,4) X(54,8,5)
#define PATHS_IO6(X) X(55,0,6) X(56,6,0) X(57,1,1) X(58,2,2) X(59,3,3) X(60,4,4) X(61,5,5) X(62,6,6) X(63,7,7) X(64,8,8)
#define PATHS_IO7(X) X(65,0,7) X(66,7,0) X(67,2,3) X(68,3,2) X(69,4,5) X(70,5,4) X(71,6,7) X(72,7,6) X(73,7,8) X(74,8,7)
#define PATHS_IO8(X) X(75,0,8) X(76,8,0) X(77,1,1) X(78,3,3) X(79,5,5) X(80,6,8) X(81,7,7) X(82,8,6)

#define NSLOT 83

// Compile-time perfect-hash table: (a*81 + b*9 + c) -> slot, 0xFF = absent.
struct SlotTbl { unsigned char m[729]; };
static constexpr SlotTbl make_slot_tbl() {
    SlotTbl t{};
    for (int i = 0; i < 729; ++i) t.m[i] = 0xFF;
#define X(s, a, b) t.m[(a) * 81 + (b) * 9 + 0] = (unsigned char)(s);
    PATHS_IO0(X)
#undef X
#define X(s, a, b) t.m[(a) * 81 + (b) * 9 + 1] = (unsigned char)(s);
    PATHS_IO1(X)
#undef X
#define X(s, a, b) t.m[(a) * 81 + (b) * 9 + 2] = (unsigned char)(s);
    PATHS_IO2(X)
#undef X
#define X(s, a, b) t.m[(a) * 81 + (b) * 9 + 3] = (unsigned char)(s);
    PATHS_IO3(X)
#undef X
#define X(s, a, b) t.m[(a) * 81 + (b) * 9 + 4] = (unsigned char)(s);
    PATHS_IO4(X)
#undef X
#define X(s, a, b) t.m[(a) * 81 + (b) * 9 + 5] = (unsigned char)(s);
    PATHS_IO5(X)
#undef X
#define X(s, a, b) t.m[(a) * 81 + (b) * 9 + 6] = (unsigned char)(s);
    PATHS_IO6(X)
#undef X
#define X(s, a, b) t.m[(a) * 81 + (b) * 9 + 7] = (unsigned char)(s);
    PATHS_IO7(X)
#undef X
#define X(s, a, b) t.m[(a) * 81 + (b) * 9 + 8] = (unsigned char)(s);
    PATHS_IO8(X)
#undef X
    return t;
}
__constant__ SlotTbl c_slot = make_slot_tbl();

#define NTHREADS 128
#define ATOMS_PER_BLOCK 4   // one warp per atom, 32 float4-threads per row

__global__ __launch_bounds__(NTHREADS)
void so3_tp_kernel(const float* __restrict__ x1,
                   const float* __restrict__ x2,
                   float* __restrict__ out,
                   int natoms,
                   const float* __restrict__ cg,
                   const int* __restrict__ i1,
                   const int* __restrict__ i2,
                   const int* __restrict__ io,
                   int P) {
    __shared__ float s_cgf[NSLOT];

    const int tid  = threadIdx.x;
    const int a_in = tid >> 5;          // atom within block
    const int lane = tid & 31;          // float4 index within 128-feature row
    const long long atom = (long long)blockIdx.x * ATOMS_PER_BLOCK + a_in;
    const int active = atom < natoms;

    const long long base = atom * 1152 + (long long)lane * 4;  // floats

    // ---- Phase A: 18 streaming evict-first LDG.128s issued first ----
    ulonglong2 x1r[9], x2r[9];
    if (active) {
#pragma unroll
        for (int s = 0; s < 9; ++s) {
            asm("ld.global.cs.v2.u64 {%0, %1}, [%2];"
                : "=l"(x1r[s].x), "=l"(x1r[s].y)
                : "l"(x1 + base + s * 128));
            asm("ld.global.cs.v2.u64 {%0, %1}, [%2];"
                : "=l"(x2r[s].x), "=l"(x2r[s].y)
                : "l"(x2 + base + s * 128));
        }
    }

    // ---- Phase B: O(P) perfect-hash structure matching (hidden) ----
    if (tid < NSLOT) s_cgf[tid] = 0.0f;
    __syncthreads();

    int ok = 1;
    for (int p = tid; p < P; p += NTHREADS) {
        const int a = __ldg(i1 + p), b = __ldg(i2 + p), c = __ldg(io + p);
        const float v = __ldg(cg + p);
        if (a >= 0 && a <= 8 && b >= 0 && b <= 8 && c >= 0 && c <= 8) {
            const unsigned char slot = c_slot.m[a * 81 + b * 9 + c];
            if (slot != 0xFF)
                atomicAdd(&s_cgf[slot], v);
            else
                ok = 0;
        } else {
            ok = 0;
        }
    }
    // Single barrier: publishes s_cgf AND reduces structure validity.
    const int ok_all = __syncthreads_and(ok);

    if (!active) return;

    if (ok_all) {
        // ---- fast path: per-io-group compute + immediate .cs store ----
        unsigned long long accx, accy, t0, t1;
#define XG(s, a, b)                                                         \
        {                                                                   \
            const float cgf = s_cgf[s];                                     \
            unsigned long long cg2;                                         \
            asm("mov.b64 %0, {%1, %1};" : "=l"(cg2) : "f"(cgf));            \
            asm("mul.rn.f32x2 %0, %1, %2;"                                  \
                : "=l"(t0) : "l"(x1r[a].x), "l"(x2r[b].x));                 \
            asm("mul.rn.f32x2 %0, %1, %2;"                                  \
                : "=l"(t1) : "l"(x1r[a].y), "l"(x2r[b].y));                 \
            asm("fma.rn.f32x2 %0, %1, %2, %3;"                              \
                : "=l"(accx) : "l"(t0), "l"(cg2), "l"(accx));               \
            asm("fma.rn.f32x2 %0, %1, %2, %3;"                              \
                : "=l"(accy) : "l"(t1), "l"(cg2), "l"(accy));               \
        }
#define GROUP(c, LIST)                                                      \
        accx = 0ull; accy = 0ull;                                           \
        LIST(XG)                                                            \
        asm volatile("st.global.cs.v2.u64 [%0], {%1, %2};"                  \
                     :: "l"(out + base + (c) * 128), "l"(accx), "l"(accy)   \
                     : "memory");

        GROUP(0, PATHS_IO0)
        GROUP(1, PATHS_IO1)
        GROUP(2, PATHS_IO2)
        GROUP(3, PATHS_IO3)
        GROUP(4, PATHS_IO4)
        GROUP(5, PATHS_IO5)
        GROUP(6, PATHS_IO6)
        GROUP(7, PATHS_IO7)
        GROUP(8, PATHS_IO8)
#undef GROUP
#undef XG
    } else {
        // ---- generic fallback: always correct for any sparse structure ----
        float4 acc[9];
#pragma unroll
        for (int s = 0; s < 9; ++s) acc[s] = make_float4(0.f, 0.f, 0.f, 0.f);
#pragma unroll 1
        for (int p = 0; p < P; ++p) {
            const int a = i1[p], b = i2[p], c = io[p];
            if (a < 0 || a > 8 || b < 0 || b > 8 || c < 0 || c > 8) continue;
            const float v = cg[p];
            const float4 u = *reinterpret_cast<const float4*>(x1 + base + a * 128);
            const float4 w = *reinterpret_cast<const float4*>(x2 + base + b * 128);
            acc[c].x += v * u.x * w.x;
            acc[c].y += v * u.y * w.y;
            acc[c].z += v * u.z * w.z;
            acc[c].w += v * u.w * w.w;
        }
#pragma unroll
        for (int s = 0; s < 9; ++s)
            *reinterpret_cast<float4*>(out + base + s * 128) = acc[s];
    }
}

extern "C" void kernel_launch(void* const* d_in, const int* in_sizes, int n_in,
                              void* d_out, int out_size) {
    const float* x1 = (const float*)d_in[0];
    const float* x2 = (const float*)d_in[1];
    const float* cg = (const float*)d_in[2];
    const int*   i1 = (const int*)d_in[3];
    const int*   i2 = (const int*)d_in[4];
    const int*   io = (const int*)d_in[5];
    float* out = (float*)d_out;

    const int P      = in_sizes[2];
    const int natoms = in_sizes[0] / (9 * 128);

    const int nblocks = (natoms + ATOMS_PER_BLOCK - 1) / ATOMS_PER_BLOCK;
    so3_tp_kernel<<<nblocks, NTHREADS>>>(x1, x2, out, natoms, cg, i1, i2, io, P);
}